// round 13
// baseline (speedup 1.0000x reference)
#include <cuda_runtime.h>
#include <math.h>

#define BB 2048
#define NN 100
#define GG 100
#define EE 128

typedef unsigned long long ull;

__device__ __forceinline__ ull bcast2(float a) {
    ull r; asm("mov.b64 %0, {%1,%1};" : "=l"(r) : "f"(a)); return r;
}
__device__ __forceinline__ void unpack2(ull v, float& lo, float& hi) {
    asm("mov.b64 {%0,%1}, %2;" : "=f"(lo), "=f"(hi) : "l"(v));
}
__device__ __forceinline__ ull ffma2(ull a, ull b, ull c) {
    ull d; asm("fma.rn.f32x2 %0, %1, %2, %3;" : "=l"(d) : "l"(a), "l"(b), "l"(c));
    return d;
}
__device__ __forceinline__ float tanh_acc(float x) {
    float ax = fabsf(x);
    float e = __expf(-2.0f * ax);
    float t = __fdividef(1.0f - e, 1.0f + e);
    return copysignf(t, x);
}

// ---- global scratch (static __device__ arrays; no runtime allocation) ------
__device__ float g_Wfl[EE * 128];
__device__ float g_qg[BB * 128];
__device__ float g_k[(size_t)BB * NN * EE];   // k  -> later mh
__device__ float g_v[(size_t)BB * NN * EE];   // v
__device__ float g_q[(size_t)BB * NN * EE];   // q  -> later attn

// ---- prep: Wfl = Wq_first + Wq_last ---------------------------------------
__global__ void prep_kernel(const float* __restrict__ Wqf,
                            const float* __restrict__ Wql) {
    int i = blockIdx.x * blockDim.x + threadIdx.x;
    if (i < EE * 128) g_Wfl[i] = Wqf[i] + Wql[i];
}

// ---- qg: per-batch graph-mean query ---------------------------------------
__global__ void qg_kernel(const float* __restrict__ enc,
                          const float* __restrict__ Wqg) {
    __shared__ float sG[EE];
    const int b = blockIdx.x, j = threadIdx.x;      // 128 threads
    const float* e0 = enc + (size_t)b * NN * EE + j;
    float s = 0.f;
    #pragma unroll 4
    for (int n = 0; n < NN; ++n) s += e0[n * EE];
    sG[j] = s * (1.0f / NN);
    __syncthreads();
    float a = 0.f;
    #pragma unroll 4
    for (int e = 0; e < EE; ++e) a += sG[e] * Wqg[e * 128 + j];
    g_qg[b * 128 + j] = a;
}

// ---- batched GEMM: out[r][j] = A[r][:] @ W[:,j] (+bias) (+pervec[b]) -------
// grid.x = 1600 (128 rows per CTA), 512 threads.
#define GEMM_SMEM_FLOATS (16896 + 16896 + 16384)   // sROW, sAT, sW
__global__ __launch_bounds__(512, 1)
void gemm_kernel(const float* __restrict__ A, const float* __restrict__ W,
                 float* __restrict__ outp, const float* __restrict__ bias,
                 const float* __restrict__ pervec) {
    extern __shared__ float sm[];
    float* sROW = sm;              // [128][132]
    float* sAT  = sm + 16896;     // [128][132]  (e-major: AT[e][r])
    float* sW   = sm + 33792;     // [128][128]
    const int tid  = threadIdx.x;
    const int lane = tid & 31;
    const int warp = tid >> 5;     // 0..15
    const long long row0 = (long long)blockIdx.x * 128;

    // stage W and A rows (coalesced)
    for (int i = tid; i < 128 * 32; i += 512) {
        int r = i >> 5, c4 = (i & 31) * 4;
        *reinterpret_cast<float4*>(sW + r * 128 + c4) =
            *reinterpret_cast<const float4*>(W + r * 128 + c4);
        *reinterpret_cast<float4*>(sROW + r * 132 + c4) =
            *reinterpret_cast<const float4*>(A + (row0 + r) * 128 + c4);
    }
    __syncthreads();

    // 4x4-block transpose sROW -> sAT
    #pragma unroll
    for (int t = 0; t < 2; ++t) {
        const int e4 = (warp + t * 16) * 4;
        const int r4 = lane * 4;
        float4 rv[4];
        #pragma unroll
        for (int i = 0; i < 4; ++i)
            rv[i] = *reinterpret_cast<const float4*>(sROW + (r4 + i) * 132 + e4);
        #pragma unroll
        for (int j = 0; j < 4; ++j) {
            float4 o;
            o.x = (&rv[0].x)[j]; o.y = (&rv[1].x)[j];
            o.z = (&rv[2].x)[j]; o.w = (&rv[3].x)[j];
            *reinterpret_cast<float4*>(sAT + (e4 + j) * 132 + r4) = o;
        }
    }
    __syncthreads();

    // compute: warp -> rows r0..r0+7, lane -> cols j0..j0+3
    const int r0 = warp * 8;
    const int j0 = lane * 4;
    ull acc[4][4];
    #pragma unroll
    for (int p = 0; p < 4; ++p)
        #pragma unroll
        for (int c = 0; c < 4; ++c) acc[p][c] = 0ULL;

    #pragma unroll 4
    for (int e = 0; e < EE; ++e) {
        const float* ap = sAT + e * 132 + r0;
        ulonglong2 A01 = *reinterpret_cast<const ulonglong2*>(ap);      // rows r0..r0+3
        ulonglong2 A23 = *reinterpret_cast<const ulonglong2*>(ap + 4);  // rows r0+4..r0+7
        float4 w4 = *reinterpret_cast<const float4*>(sW + e * 128 + j0);
        ull w0 = bcast2(w4.x), w1 = bcast2(w4.y);
        ull w2 = bcast2(w4.z), w3 = bcast2(w4.w);
        acc[0][0] = ffma2(A01.x, w0, acc[0][0]); acc[0][1] = ffma2(A01.x, w1, acc[0][1]);
        acc[0][2] = ffma2(A01.x, w2, acc[0][2]); acc[0][3] = ffma2(A01.x, w3, acc[0][3]);
        acc[1][0] = ffma2(A01.y, w0, acc[1][0]); acc[1][1] = ffma2(A01.y, w1, acc[1][1]);
        acc[1][2] = ffma2(A01.y, w2, acc[1][2]); acc[1][3] = ffma2(A01.y, w3, acc[1][3]);
        acc[2][0] = ffma2(A23.x, w0, acc[2][0]); acc[2][1] = ffma2(A23.x, w1, acc[2][1]);
        acc[2][2] = ffma2(A23.x, w2, acc[2][2]); acc[2][3] = ffma2(A23.x, w3, acc[2][3]);
        acc[3][0] = ffma2(A23.y, w0, acc[3][0]); acc[3][1] = ffma2(A23.y, w1, acc[3][1]);
        acc[3][2] = ffma2(A23.y, w2, acc[3][2]); acc[3][3] = ffma2(A23.y, w3, acc[3][3]);
    }

    float4 badd = make_float4(0.f, 0.f, 0.f, 0.f);
    if (bias) badd = *reinterpret_cast<const float4*>(bias + j0);

    #pragma unroll
    for (int p = 0; p < 4; ++p) {
        const long long r  = row0 + r0 + 2 * p;
        float4 lo4, hi4;
        unpack2(acc[p][0], lo4.x, hi4.x);
        unpack2(acc[p][1], lo4.y, hi4.y);
        unpack2(acc[p][2], lo4.z, hi4.z);
        unpack2(acc[p][3], lo4.w, hi4.w);
        lo4.x += badd.x; lo4.y += badd.y; lo4.z += badd.z; lo4.w += badd.w;
        hi4.x += badd.x; hi4.y += badd.y; hi4.z += badd.z; hi4.w += badd.w;
        if (pervec) {
            int b0 = (int)(r / 100), b1 = (int)((r + 1) / 100);
            float4 p0 = *reinterpret_cast<const float4*>(pervec + b0 * 128 + j0);
            float4 p1 = *reinterpret_cast<const float4*>(pervec + b1 * 128 + j0);
            lo4.x += p0.x; lo4.y += p0.y; lo4.z += p0.z; lo4.w += p0.w;
            hi4.x += p1.x; hi4.y += p1.y; hi4.z += p1.z; hi4.w += p1.w;
        }
        *reinterpret_cast<float4*>(outp + r * 128 + j0) = lo4;
        *reinterpret_cast<float4*>(outp + (r + 1) * 128 + j0) = hi4;
    }
}

// ---- attention: grid (2048, 2) head-halves, 512 threads, 2 CTA/SM ---------
#define ATTN_SMEM_FLOATS (6800 + 6800 + 10000)   // sK, sV, sM
__global__ __launch_bounds__(512, 2)
void attn_kernel(const float* __restrict__ maskp) {
    extern __shared__ float sm[];
    float* sK = sm;            // [100][68] (4 heads of this half)
    float* sV = sm + 6800;
    float* sM = sm + 13600;    // maskT [n][g]
    const int b    = blockIdx.x;
    const int half = blockIdx.y;
    const int tid  = threadIdx.x;
    const size_t rbase = (size_t)b * NN * EE + half * 64;

    for (int idx = tid; idx < NN * 16; idx += 512) {
        int n = idx >> 4, c4 = (idx & 15) * 4;
        *reinterpret_cast<float4*>(sK + n * 68 + c4) =
            *reinterpret_cast<const float4*>(g_k + rbase + (size_t)n * 128 + c4);
        *reinterpret_cast<float4*>(sV + n * 68 + c4) =
            *reinterpret_cast<const float4*>(g_v + rbase + (size_t)n * 128 + c4);
    }
    for (int idx = tid; idx < (GG * NN) / 4; idx += 512) {
        int g = idx / 25, n4 = (idx % 25) * 4;
        float4 mv = *reinterpret_cast<const float4*>(
            maskp + (size_t)b * GG * NN + g * NN + n4);
        sM[(n4 + 0) * 100 + g] = mv.x;
        sM[(n4 + 1) * 100 + g] = mv.y;
        sM[(n4 + 2) * 100 + g] = mv.z;
        sM[(n4 + 3) * 100 + g] = mv.w;
    }

    const int g  = tid & 127;
    const int hl = tid >> 7;        // 0..3
    const int c0 = hl * 16;
    const bool act = (g < GG);
    ull q2[8];
    if (act) {
        const float* qp = g_q + rbase + (size_t)g * 128 + c0;
        #pragma unroll
        for (int j = 0; j < 8; ++j)
            q2[j] = *reinterpret_cast<const ull*>(qp + 2 * j);
    }
    __syncthreads();

    if (act) {
        ull acc2[8];
        #pragma unroll
        for (int j = 0; j < 8; ++j) acc2[j] = 0ULL;
        float m = -1e30f, l = 0.f;
        const float* kb = sK + c0;
        const float* vb = sV + c0;
        for (int n = 0; n < NN; ++n) {
            const ulonglong2* kp = reinterpret_cast<const ulonglong2*>(kb + n * 68);
            ulonglong2 k0 = kp[0], k1 = kp[1], k2 = kp[2], k3 = kp[3];
            ull sa = 0ULL, sb = 0ULL;
            sa = ffma2(q2[0], k0.x, sa); sb = ffma2(q2[1], k0.y, sb);
            sa = ffma2(q2[2], k1.x, sa); sb = ffma2(q2[3], k1.y, sb);
            sa = ffma2(q2[4], k2.x, sa); sb = ffma2(q2[5], k2.y, sb);
            sa = ffma2(q2[6], k3.x, sa); sb = ffma2(q2[7], k3.y, sb);
            float x0, x1, y0, y1;
            unpack2(sa, x0, x1); unpack2(sb, y0, y1);
            float s = ((x0 + y0) + (x1 + y1)) * 0.25f + sM[n * 100 + g];
            const ulonglong2* vp = reinterpret_cast<const ulonglong2*>(vb + n * 68);
            ulonglong2 v0 = vp[0], v1 = vp[1], v2 = vp[2], v3 = vp[3];
            if (s > m) {
                float c = __expf(m - s);
                l = l * c + 1.0f;
                ull cc = bcast2(c);
                acc2[0] = ffma2(acc2[0], cc, v0.x); acc2[1] = ffma2(acc2[1], cc, v0.y);
                acc2[2] = ffma2(acc2[2], cc, v1.x); acc2[3] = ffma2(acc2[3], cc, v1.y);
                acc2[4] = ffma2(acc2[4], cc, v2.x); acc2[5] = ffma2(acc2[5], cc, v2.y);
                acc2[6] = ffma2(acc2[6], cc, v3.x); acc2[7] = ffma2(acc2[7], cc, v3.y);
                m = s;
            } else {
                float p = __expf(s - m);
                l += p;
                ull pp = bcast2(p);
                acc2[0] = ffma2(v0.x, pp, acc2[0]); acc2[1] = ffma2(v0.y, pp, acc2[1]);
                acc2[2] = ffma2(v1.x, pp, acc2[2]); acc2[3] = ffma2(v1.y, pp, acc2[3]);
                acc2[4] = ffma2(v2.x, pp, acc2[4]); acc2[5] = ffma2(v2.y, pp, acc2[5]);
                acc2[6] = ffma2(v3.x, pp, acc2[6]); acc2[7] = ffma2(v3.y, pp, acc2[7]);
            }
        }
        const float rl = __fdividef(1.f, l);
        float* dst = g_q + rbase + (size_t)g * 128 + c0;   // attn overwrites q
        #pragma unroll
        for (int j = 0; j < 4; ++j) {
            float4 o;
            unpack2(acc2[2 * j + 0], o.x, o.y);
            unpack2(acc2[2 * j + 1], o.z, o.w);
            o.x *= rl; o.y *= rl; o.z *= rl; o.w *= rl;
            *reinterpret_cast<float4*>(dst + 4 * j) = o;
        }
    }
}

// ---- pointer scores + masked softmax: grid 2048, 1024 threads -------------
#define PTR_SMEM_FLOATS (13312 + 13312 + 10400)   // sMT, sET, sS
__global__ __launch_bounds__(1024, 1)
void pointer_kernel(const float* __restrict__ enc, const float* __restrict__ maskp,
                    float* __restrict__ outp) {
    extern __shared__ float sm[];
    float* sMT = sm;            // mhT [128][104]
    float* sET = sm + 13312;    // encT [128][104]
    float* sS  = sm + 26624;    // S [100][104]
    const int b    = blockIdx.x;
    const int tid  = threadIdx.x;
    const int lane = tid & 31;
    const int warp = tid >> 5;

    for (int idx = tid; idx < NN * 32; idx += 1024) {
        int r = idx >> 5, e4 = (idx & 31) * 4;
        float4 mh4 = *reinterpret_cast<const float4*>(
            g_k + ((size_t)b * NN + r) * 128 + e4);          // mh lives in g_k
        sMT[(e4 + 0) * 104 + r] = mh4.x;
        sMT[(e4 + 1) * 104 + r] = mh4.y;
        sMT[(e4 + 2) * 104 + r] = mh4.z;
        sMT[(e4 + 3) * 104 + r] = mh4.w;
        float4 ev = *reinterpret_cast<const float4*>(
            enc + ((size_t)b * NN + r) * 128 + e4);
        sET[(e4 + 0) * 104 + r] = ev.x;
        sET[(e4 + 1) * 104 + r] = ev.y;
        sET[(e4 + 2) * 104 + r] = ev.z;
        sET[(e4 + 3) * 104 + r] = ev.w;
    }
    __syncthreads();

    if (warp < 25 && lane < 25) {
        const int g0 = warp * 4;
        const int n0 = lane * 4;
        ull acc[2][4];
        #pragma unroll
        for (int i = 0; i < 2; ++i)
            #pragma unroll
            for (int c = 0; c < 4; ++c) acc[i][c] = 0ULL;
        #pragma unroll 4
        for (int e = 0; e < EE; ++e) {
            ull a0 = *reinterpret_cast<const ull*>(sMT + e * 104 + g0);
            ull a1 = *reinterpret_cast<const ull*>(sMT + e * 104 + g0 + 2);
            float4 b4 = *reinterpret_cast<const float4*>(sET + e * 104 + n0);
            ull w0 = bcast2(b4.x), w1 = bcast2(b4.y);
            ull w2 = bcast2(b4.z), w3 = bcast2(b4.w);
            acc[0][0] = ffma2(a0, w0, acc[0][0]); acc[0][1] = ffma2(a0, w1, acc[0][1]);
            acc[0][2] = ffma2(a0, w2, acc[0][2]); acc[0][3] = ffma2(a0, w3, acc[0][3]);
            acc[1][0] = ffma2(a1, w0, acc[1][0]); acc[1][1] = ffma2(a1, w1, acc[1][1]);
            acc[1][2] = ffma2(a1, w2, acc[1][2]); acc[1][3] = ffma2(a1, w3, acc[1][3]);
        }
        const float rsE = 0.08838834764831845f;   // 1/sqrt(128)
        #pragma unroll
        for (int r = 0; r < 4; ++r) {
            float4 o;
            float lo, hi;
            unpack2(acc[r >> 1][0], lo, hi); o.x = 10.f * tanh_acc(((r & 1) ? hi : lo) * rsE);
            unpack2(acc[r >> 1][1], lo, hi); o.y = 10.f * tanh_acc(((r & 1) ? hi : lo) * rsE);
            unpack2(acc[r >> 1][2], lo, hi); o.z = 10.f * tanh_acc(((r & 1) ? hi : lo) * rsE);
            unpack2(acc[r >> 1][3], lo, hi); o.w = 10.f * tanh_acc(((r & 1) ? hi : lo) * rsE);
            *reinterpret_cast<float4*>(sS + (g0 + r) * 104 + n0) = o;
        }
    }
    __syncthreads();

    const float* maskB = maskp + (size_t)b * GG * NN;
    float*       outB  = outp + (size_t)b * GG * NN;
    for (int gr = warp; gr < GG; gr += 32) {
        float v[4];
        float mx = -1e30f;
        #pragma unroll
        for (int r = 0; r < 4; ++r) {
            const int n = lane + r * 32;
            float x = -1e30f;
            if (n < NN) x = sS[gr * 104 + n] + maskB[gr * NN + n];
            v[r] = x;
            mx = fmaxf(mx, x);
        }
        #pragma unroll
        for (int o = 16; o > 0; o >>= 1) mx = fmaxf(mx, __shfl_xor_sync(~0u, mx, o));
        float sum = 0.f;
        #pragma unroll
        for (int r = 0; r < 4; ++r) {
            const int n = lane + r * 32;
            float e = (n < NN) ? __expf(v[r] - mx) : 0.f;
            v[r] = e;
            sum += e;
        }
        #pragma unroll
        for (int o = 16; o > 0; o >>= 1) sum += __shfl_xor_sync(~0u, sum, o);
        const float inv = __fdividef(1.f, sum);
        #pragma unroll
        for (int r = 0; r < 4; ++r) {
            const int n = lane + r * 32;
            if (n < NN) outB[gr * NN + n] = v[r] * inv;
        }
    }
}

extern "C" void kernel_launch(void* const* d_in, const int* in_sizes, int n_in,
                              void* d_out, int out_size) {
    const float* enc  = (const float*)d_in[0];
    const float* last = (const float*)d_in[1];
    const float* mask = (const float*)d_in[2];
    const float* Wqg  = (const float*)d_in[3];
    const float* Wqf  = (const float*)d_in[4];
    const float* Wql  = (const float*)d_in[5];
    const float* Wk   = (const float*)d_in[6];
    const float* Wv   = (const float*)d_in[7];
    const float* Wc   = (const float*)d_in[8];
    const float* bc   = (const float*)d_in[9];
    float* out = (float*)d_out;

    static int configured = 0;
    if (!configured) {
        cudaFuncSetAttribute(gemm_kernel, cudaFuncAttributeMaxDynamicSharedMemorySize,
                             GEMM_SMEM_FLOATS * 4);
        cudaFuncSetAttribute(attn_kernel, cudaFuncAttributeMaxDynamicSharedMemorySize,
                             ATTN_SMEM_FLOATS * 4);
        cudaFuncSetAttribute(pointer_kernel, cudaFuncAttributeMaxDynamicSharedMemorySize,
                             PTR_SMEM_FLOATS * 4);
        configured = 1;
    }

    float* gk; cudaGetSymbolAddress((void**)&gk, g_k);
    float* gv; cudaGetSymbolAddress((void**)&gv, g_v);
    float* gq; cudaGetSymbolAddress((void**)&gq, g_q);
    float* gqg; cudaGetSymbolAddress((void**)&gqg, g_qg);
    float* gwfl; cudaGetSymbolAddress((void**)&gwfl, g_Wfl);

    prep_kernel<<<(EE * 128 + 255) / 256, 256>>>(Wqf, Wql);
    qg_kernel<<<BB, 128>>>(enc, Wqg);

    gemm_kernel<<<1600, 512, GEMM_SMEM_FLOATS * 4>>>(enc, Wk, gk, nullptr, nullptr);
    gemm_kernel<<<1600, 512, GEMM_SMEM_FLOATS * 4>>>(enc, Wv, gv, nullptr, nullptr);
    gemm_kernel<<<1600, 512, GEMM_SMEM_FLOATS * 4>>>(last, gwfl, gq, nullptr, gqg);

    attn_kernel<<<dim3(BB, 2), 512, ATTN_SMEM_FLOATS * 4>>>(mask);

    gemm_kernel<<<1600, 512, GEMM_SMEM_FLOATS * 4>>>(gq, Wc, gk, bc, nullptr);

    pointer_kernel<<<BB, 1024, PTR_SMEM_FLOATS * 4>>>(enc, mask, out);
}

// round 16
// speedup vs baseline: 1.1092x; 1.1092x over previous
#include <cuda_runtime.h>
#include <math.h>

#define BB 2048
#define NN 100
#define GG 100
#define EE 128

typedef unsigned long long ull;

__device__ __forceinline__ ull bcast2(float a) {
    ull r; asm("mov.b64 %0, {%1,%1};" : "=l"(r) : "f"(a)); return r;
}
__device__ __forceinline__ void unpack2(ull v, float& lo, float& hi) {
    asm("mov.b64 {%0,%1}, %2;" : "=f"(lo), "=f"(hi) : "l"(v));
}
__device__ __forceinline__ ull ffma2(ull a, ull b, ull c) {
    ull d; asm("fma.rn.f32x2 %0, %1, %2, %3;" : "=l"(d) : "l"(a), "l"(b), "l"(c));
    return d;
}
__device__ __forceinline__ ull fmul2(ull a, ull b) {
    ull d; asm("mul.rn.f32x2 %0, %1, %2;" : "=l"(d) : "l"(a), "l"(b)); return d;
}
__device__ __forceinline__ float tanh_acc(float x) {
    float ax = fabsf(x);
    float e = __expf(-2.0f * ax);
    float t = __fdividef(1.0f - e, 1.0f + e);
    return copysignf(t, x);
}

__device__ __forceinline__ void cp16(void* smem_ptr, const void* gptr) {
    unsigned s = (unsigned)__cvta_generic_to_shared(smem_ptr);
    asm volatile("cp.async.cg.shared.global [%0], [%1], 16;" :: "r"(s), "l"(gptr));
}
#define CP_COMMIT() asm volatile("cp.async.commit_group;")
#define CP_WAIT0()  asm volatile("cp.async.wait_group 0;")

// ---- global scratch ---------------------------------------------------------
__device__ float g_Wfl[EE * 128];
__device__ float g_qg[BB * 128];
__device__ float g_k[(size_t)BB * NN * EE];   // k -> later mh
__device__ float g_v[(size_t)BB * NN * EE];   // v
__device__ float g_q[(size_t)BB * NN * EE];   // q -> later attn

__global__ void prep_kernel(const float* __restrict__ Wqf,
                            const float* __restrict__ Wql) {
    int i = blockIdx.x * blockDim.x + threadIdx.x;
    if (i < EE * 128) g_Wfl[i] = Wqf[i] + Wql[i];
}

__global__ void qg_kernel(const float* __restrict__ enc,
                          const float* __restrict__ Wqg) {
    __shared__ float sG[EE];
    const int b = blockIdx.x, j = threadIdx.x;      // 128 threads
    const float* e0 = enc + (size_t)b * NN * EE + j;
    float s = 0.f;
    #pragma unroll 4
    for (int n = 0; n < NN; ++n) s += e0[n * EE];
    sG[j] = s * (1.0f / NN);
    __syncthreads();
    float a = 0.f;
    #pragma unroll 4
    for (int e = 0; e < EE; ++e) a += sG[e] * Wqg[e * 128 + j];
    g_qg[b * 128 + j] = a;
}

// ---- projection building blocks --------------------------------------------
#define PROJ_SMEM_FLOATS (16896 + 16896 + 16384)   // sROW, sAT, sW

__device__ __forceinline__ void stageA(float* sROW, const float* __restrict__ A,
                                       long long row0, int tid) {
    for (int i = tid; i < 128 * 32; i += 512) {
        int r = i >> 5, c4 = (i & 31) * 4;
        cp16(sROW + r * 132 + c4, A + (row0 + r) * 128 + c4);
    }
}
__device__ __forceinline__ void stageW(float* sW, const float* __restrict__ W,
                                       int tid) {
    for (int i = tid; i < 128 * 32; i += 512) {
        int r = i >> 5, c4 = (i & 31) * 4;
        cp16(sW + r * 128 + c4, W + r * 128 + c4);
    }
}

// conflict-free 4x4-block transpose sROW[r][e] -> sAT[e][r] (both stride 132)
__device__ __forceinline__ void transpose128(const float* sROW, float* sAT,
                                             int warp, int lane) {
    #pragma unroll
    for (int t = 0; t < 2; ++t) {
        const int e4 = (warp + t * 16) * 4;
        const int r4 = lane * 4;
        float4 rv[4];
        #pragma unroll
        for (int i = 0; i < 4; ++i)
            rv[i] = *reinterpret_cast<const float4*>(sROW + (r4 + i) * 132 + e4);
        #pragma unroll
        for (int j = 0; j < 4; ++j) {
            float4 o;
            o.x = (&rv[0].x)[j]; o.y = (&rv[1].x)[j];
            o.z = (&rv[2].x)[j]; o.w = (&rv[3].x)[j];
            *reinterpret_cast<float4*>(sAT + (e4 + j) * 132 + r4) = o;
        }
    }
}

// one 128x128 compute pass: out[row0+r][j] = AT(:,r) . W(:,j) (+bias)(+pervec)
__device__ __forceinline__ void compute_tile(const float* sAT, const float* sW,
                                             float* __restrict__ outp,
                                             long long row0,
                                             const float* __restrict__ bias,
                                             const float* __restrict__ pervec,
                                             int warp, int lane) {
    const int r0 = warp * 8;
    const int j0 = lane * 4;
    ull acc[4][4];
    #pragma unroll
    for (int p = 0; p < 4; ++p)
        #pragma unroll
        for (int c = 0; c < 4; ++c) acc[p][c] = 0ULL;

    #pragma unroll 4
    for (int e = 0; e < EE; ++e) {
        const float* ap = sAT + e * 132 + r0;
        ulonglong2 A01 = *reinterpret_cast<const ulonglong2*>(ap);
        ulonglong2 A23 = *reinterpret_cast<const ulonglong2*>(ap + 4);
        float4 w4 = *reinterpret_cast<const float4*>(sW + e * 128 + j0);
        ull w0 = bcast2(w4.x), w1 = bcast2(w4.y);
        ull w2 = bcast2(w4.z), w3 = bcast2(w4.w);
        acc[0][0] = ffma2(A01.x, w0, acc[0][0]); acc[0][1] = ffma2(A01.x, w1, acc[0][1]);
        acc[0][2] = ffma2(A01.x, w2, acc[0][2]); acc[0][3] = ffma2(A01.x, w3, acc[0][3]);
        acc[1][0] = ffma2(A01.y, w0, acc[1][0]); acc[1][1] = ffma2(A01.y, w1, acc[1][1]);
        acc[1][2] = ffma2(A01.y, w2, acc[1][2]); acc[1][3] = ffma2(A01.y, w3, acc[1][3]);
        acc[2][0] = ffma2(A23.x, w0, acc[2][0]); acc[2][1] = ffma2(A23.x, w1, acc[2][1]);
        acc[2][2] = ffma2(A23.x, w2, acc[2][2]); acc[2][3] = ffma2(A23.x, w3, acc[2][3]);
        acc[3][0] = ffma2(A23.y, w0, acc[3][0]); acc[3][1] = ffma2(A23.y, w1, acc[3][1]);
        acc[3][2] = ffma2(A23.y, w2, acc[3][2]); acc[3][3] = ffma2(A23.y, w3, acc[3][3]);
    }

    float4 badd = make_float4(0.f, 0.f, 0.f, 0.f);
    if (bias) badd = *reinterpret_cast<const float4*>(bias + j0);

    #pragma unroll
    for (int p = 0; p < 4; ++p) {
        const long long r = row0 + r0 + 2 * p;
        float4 lo4, hi4;
        unpack2(acc[p][0], lo4.x, hi4.x);
        unpack2(acc[p][1], lo4.y, hi4.y);
        unpack2(acc[p][2], lo4.z, hi4.z);
        unpack2(acc[p][3], lo4.w, hi4.w);
        lo4.x += badd.x; lo4.y += badd.y; lo4.z += badd.z; lo4.w += badd.w;
        hi4.x += badd.x; hi4.y += badd.y; hi4.z += badd.z; hi4.w += badd.w;
        if (pervec) {
            int b0 = (int)(r / 100), b1 = (int)((r + 1) / 100);
            float4 p0 = *reinterpret_cast<const float4*>(pervec + b0 * 128 + j0);
            float4 p1 = *reinterpret_cast<const float4*>(pervec + b1 * 128 + j0);
            lo4.x += p0.x; lo4.y += p0.y; lo4.z += p0.z; lo4.w += p0.w;
            hi4.x += p1.x; hi4.y += p1.y; hi4.z += p1.z; hi4.w += p1.w;
        }
        *reinterpret_cast<float4*>(outp + r * 128 + j0) = lo4;
        *reinterpret_cast<float4*>(outp + (r + 1) * 128 + j0) = hi4;
    }
}

// ---- fused k+v projection: 256 rows per CTA, grid 800 -----------------------
__global__ __launch_bounds__(512, 1)
void proj_kv_kernel(const float* __restrict__ A,
                    const float* __restrict__ Wk, const float* __restrict__ Wv) {
    extern __shared__ float sm[];
    float* sROW = sm;
    float* sAT  = sm + 16896;
    float* sW   = sm + 33792;
    const int tid  = threadIdx.x;
    const int lane = tid & 31;
    const int warp = tid >> 5;
    const long long row0 = (long long)blockIdx.x * 256;
    float* gk; float* gv;
    { gk = g_k; gv = g_v; }

    stageA(sROW, A, row0, tid);
    stageW(sW, Wk, tid);
    CP_COMMIT(); CP_WAIT0();
    __syncthreads();
    transpose128(sROW, sAT, warp, lane);           // AT = chunk0
    __syncthreads();
    stageA(sROW, A, row0 + 128, tid);              // prefetch chunk1
    CP_COMMIT();
    compute_tile(sAT, sW, gk, row0, nullptr, nullptr, warp, lane);   // k0
    __syncthreads();
    stageW(sW, Wv, tid);
    CP_COMMIT(); CP_WAIT0();                        // Wv + A1 resident
    __syncthreads();
    compute_tile(sAT, sW, gv, row0, nullptr, nullptr, warp, lane);   // v0
    __syncthreads();
    transpose128(sROW, sAT, warp, lane);            // AT = chunk1
    __syncthreads();
    compute_tile(sAT, sW, gv, row0 + 128, nullptr, nullptr, warp, lane); // v1
    __syncthreads();
    stageW(sW, Wk, tid);
    CP_COMMIT(); CP_WAIT0();
    __syncthreads();
    compute_tile(sAT, sW, gk, row0 + 128, nullptr, nullptr, warp, lane); // k1
}

// ---- single-W projection: 256 rows per CTA, grid 800 ------------------------
__global__ __launch_bounds__(512, 1)
void proj_one_kernel(const float* __restrict__ A, const float* __restrict__ W,
                     float* __restrict__ outp, const float* __restrict__ bias,
                     const float* __restrict__ pervec) {
    extern __shared__ float sm[];
    float* sROW = sm;
    float* sAT  = sm + 16896;
    float* sW   = sm + 33792;
    const int tid  = threadIdx.x;
    const int lane = tid & 31;
    const int warp = tid >> 5;
    const long long row0 = (long long)blockIdx.x * 256;

    stageA(sROW, A, row0, tid);
    stageW(sW, W, tid);
    CP_COMMIT(); CP_WAIT0();
    __syncthreads();
    transpose128(sROW, sAT, warp, lane);
    __syncthreads();
    stageA(sROW, A, row0 + 128, tid);              // prefetch chunk1
    CP_COMMIT();
    compute_tile(sAT, sW, outp, row0, bias, pervec, warp, lane);
    CP_WAIT0();
    __syncthreads();
    transpose128(sROW, sAT, warp, lane);
    __syncthreads();
    compute_tile(sAT, sW, outp, row0 + 128, bias, pervec, warp, lane);
}

// ---- attention: grid (2048, 2) head-halves, 512 threads, 2 CTA/SM ----------
#define ATTN_SMEM_FLOATS (6800 + 6800 + 10000)   // sK, sV, sM
__global__ __launch_bounds__(512, 2)
void attn_kernel(const float* __restrict__ maskp) {
    extern __shared__ float sm[];
    float* sK = sm;            // [100][68]
    float* sV = sm + 6800;
    float* sM = sm + 13600;    // maskT [n][g]
    const int b    = blockIdx.x;
    const int half = blockIdx.y;
    const int tid  = threadIdx.x;
    const size_t rbase = (size_t)b * NN * EE + half * 64;

    for (int idx = tid; idx < NN * 16; idx += 512) {
        int n = idx >> 4, c4 = (idx & 15) * 4;
        *reinterpret_cast<float4*>(sK + n * 68 + c4) =
            *reinterpret_cast<const float4*>(g_k + rbase + (size_t)n * 128 + c4);
        *reinterpret_cast<float4*>(sV + n * 68 + c4) =
            *reinterpret_cast<const float4*>(g_v + rbase + (size_t)n * 128 + c4);
    }
    for (int idx = tid; idx < (GG * NN) / 4; idx += 512) {
        int g = idx / 25, n4 = (idx % 25) * 4;
        float4 mv = *reinterpret_cast<const float4*>(
            maskp + (size_t)b * GG * NN + g * NN + n4);
        sM[(n4 + 0) * 100 + g] = mv.x;
        sM[(n4 + 1) * 100 + g] = mv.y;
        sM[(n4 + 2) * 100 + g] = mv.z;
        sM[(n4 + 3) * 100 + g] = mv.w;
    }

    const int g  = tid & 127;
    const int hl = tid >> 7;
    const int c0 = hl * 16;
    const bool act = (g < GG);
    ull q2[8];
    if (act) {
        const float* qp = g_q + rbase + (size_t)g * 128 + c0;
        #pragma unroll
        for (int j = 0; j < 8; ++j)
            q2[j] = *reinterpret_cast<const ull*>(qp + 2 * j);
    }
    __syncthreads();

    if (act) {
        ull acc2[8];
        #pragma unroll
        for (int j = 0; j < 8; ++j) acc2[j] = 0ULL;
        float m = -1e30f, l = 0.f;
        const float* kb = sK + c0;
        const float* vb = sV + c0;
        for (int n = 0; n < NN; ++n) {
            const ulonglong2* kp = reinterpret_cast<const ulonglong2*>(kb + n * 68);
            ulonglong2 k0 = kp[0], k1 = kp[1], k2 = kp[2], k3 = kp[3];
            ull sa = 0ULL, sb = 0ULL;
            sa = ffma2(q2[0], k0.x, sa); sb = ffma2(q2[1], k0.y, sb);
            sa = ffma2(q2[2], k1.x, sa); sb = ffma2(q2[3], k1.y, sb);
            sa = ffma2(q2[4], k2.x, sa); sb = ffma2(q2[5], k2.y, sb);
            sa = ffma2(q2[6], k3.x, sa); sb = ffma2(q2[7], k3.y, sb);
            float x0, x1, y0, y1;
            unpack2(sa, x0, x1); unpack2(sb, y0, y1);
            float s = ((x0 + y0) + (x1 + y1)) * 0.25f + sM[n * 100 + g];
            const ulonglong2* vp = reinterpret_cast<const ulonglong2*>(vb + n * 68);
            ulonglong2 v0 = vp[0], v1 = vp[1], v2 = vp[2], v3 = vp[3];
            // branchless online softmax
            float mn = fmaxf(m, s);
            float c  = __expf(m - mn);
            float p  = __expf(s - mn);
            l = l * c + p;
            m = mn;
            ull cc = bcast2(c), pp = bcast2(p);
            acc2[0] = ffma2(acc2[0], cc, fmul2(v0.x, pp));
            acc2[1] = ffma2(acc2[1], cc, fmul2(v0.y, pp));
            acc2[2] = ffma2(acc2[2], cc, fmul2(v1.x, pp));
            acc2[3] = ffma2(acc2[3], cc, fmul2(v1.y, pp));
            acc2[4] = ffma2(acc2[4], cc, fmul2(v2.x, pp));
            acc2[5] = ffma2(acc2[5], cc, fmul2(v2.y, pp));
            acc2[6] = ffma2(acc2[6], cc, fmul2(v3.x, pp));
            acc2[7] = ffma2(acc2[7], cc, fmul2(v3.y, pp));
        }
        const float rl = __fdividef(1.f, l);
        float* dst = g_q + rbase + (size_t)g * 128 + c0;   // attn overwrites q
        #pragma unroll
        for (int j = 0; j < 4; ++j) {
            float4 o;
            unpack2(acc2[2 * j + 0], o.x, o.y);
            unpack2(acc2[2 * j + 1], o.z, o.w);
            o.x *= rl; o.y *= rl; o.z *= rl; o.w *= rl;
            *reinterpret_cast<float4*>(dst + 4 * j) = o;
        }
    }
}

// ---- pointer scores + masked softmax ---------------------------------------
#define PTR_SMEM_FLOATS (13312 + 13312 + 10400)   // sMT, sET, sS
__global__ __launch_bounds__(1024, 1)
void pointer_kernel(const float* __restrict__ enc, const float* __restrict__ maskp,
                    float* __restrict__ outp) {
    extern __shared__ float sm[];
    float* sMT = sm;            // mhT [128][104]
    float* sET = sm + 13312;    // encT [128][104]
    float* sS  = sm + 26624;    // S [100][104]
    const int b    = blockIdx.x;
    const int tid  = threadIdx.x;
    const int lane = tid & 31;
    const int warp = tid >> 5;

    for (int idx = tid; idx < NN * 32; idx += 1024) {
        int r = idx >> 5, e4 = (idx & 31) * 4;
        float4 mh4 = *reinterpret_cast<const float4*>(
            g_k + ((size_t)b * NN + r) * 128 + e4);          // mh lives in g_k
        sMT[(e4 + 0) * 104 + r] = mh4.x;
        sMT[(e4 + 1) * 104 + r] = mh4.y;
        sMT[(e4 + 2) * 104 + r] = mh4.z;
        sMT[(e4 + 3) * 104 + r] = mh4.w;
        float4 ev = *reinterpret_cast<const float4*>(
            enc + ((size_t)b * NN + r) * 128 + e4);
        sET[(e4 + 0) * 104 + r] = ev.x;
        sET[(e4 + 1) * 104 + r] = ev.y;
        sET[(e4 + 2) * 104 + r] = ev.z;
        sET[(e4 + 3) * 104 + r] = ev.w;
    }
    __syncthreads();

    if (warp < 25 && lane < 25) {
        const int g0 = warp * 4;
        const int n0 = lane * 4;
        ull acc[2][4];
        #pragma unroll
        for (int i = 0; i < 2; ++i)
            #pragma unroll
            for (int c = 0; c < 4; ++c) acc[i][c] = 0ULL;
        #pragma unroll 4
        for (int e = 0; e < EE; ++e) {
            ull a0 = *reinterpret_cast<const ull*>(sMT + e * 104 + g0);
            ull a1 = *reinterpret_cast<const ull*>(sMT + e * 104 + g0 + 2);
            float4 b4 = *reinterpret_cast<const float4*>(sET + e * 104 + n0);
            ull w0 = bcast2(b4.x), w1 = bcast2(b4.y);
            ull w2 = bcast2(b4.z), w3 = bcast2(b4.w);
            acc[0][0] = ffma2(a0, w0, acc[0][0]); acc[0][1] = ffma2(a0, w1, acc[0][1]);
            acc[0][2] = ffma2(a0, w2, acc[0][2]); acc[0][3] = ffma2(a0, w3, acc[0][3]);
            acc[1][0] = ffma2(a1, w0, acc[1][0]); acc[1][1] = ffma2(a1, w1, acc[1][1]);
            acc[1][2] = ffma2(a1, w2, acc[1][2]); acc[1][3] = ffma2(a1, w3, acc[1][3]);
        }
        const float rsE = 0.08838834764831845f;   // 1/sqrt(128)
        #pragma unroll
        for (int r = 0; r < 4; ++r) {
            float4 o;
            float lo, hi;
            unpack2(acc[r >> 1][0], lo, hi); o.x = 10.f * tanh_acc(((r & 1) ? hi : lo) * rsE);
            unpack2(acc[r >> 1][1], lo, hi); o.y = 10.f * tanh_acc(((r & 1) ? hi : lo) * rsE);
            unpack2(acc[r >> 1][2], lo, hi); o.z = 10.f * tanh_acc(((r & 1) ? hi : lo) * rsE);
            unpack2(acc[r >> 1][3], lo, hi); o.w = 10.f * tanh_acc(((r & 1) ? hi : lo) * rsE);
            *reinterpret_cast<float4*>(sS + (g0 + r) * 104 + n0) = o;
        }
    }
    __syncthreads();

    const float* maskB = maskp + (size_t)b * GG * NN;
    float*       outB  = outp + (size_t)b * GG * NN;
    for (int gr = warp; gr < GG; gr += 32) {
        float v[4];
        float mx = -1e30f;
        #pragma unroll
        for (int r = 0; r < 4; ++r) {
            const int n = lane + r * 32;
            float x = -1e30f;
            if (n < NN) x = sS[gr * 104 + n] + maskB[gr * NN + n];
            v[r] = x;
            mx = fmaxf(mx, x);
        }
        #pragma unroll
        for (int o = 16; o > 0; o >>= 1) mx = fmaxf(mx, __shfl_xor_sync(~0u, mx, o));
        float sum = 0.f;
        #pragma unroll
        for (int r = 0; r < 4; ++r) {
            const int n = lane + r * 32;
            float e = (n < NN) ? __expf(v[r] - mx) : 0.f;
            v[r] = e;
            sum += e;
        }
        #pragma unroll
        for (int o = 16; o > 0; o >>= 1) sum += __shfl_xor_sync(~0u, sum, o);
        const float inv = __fdividef(1.f, sum);
        #pragma unroll
        for (int r = 0; r < 4; ++r) {
            const int n = lane + r * 32;
            if (n < NN) outB[gr * NN + n] = v[r] * inv;
        }
    }
}

extern "C" void kernel_launch(void* const* d_in, const int* in_sizes, int n_in,
                              void* d_out, int out_size) {
    const float* enc  = (const float*)d_in[0];
    const float* last = (const float*)d_in[1];
    const float* mask = (const float*)d_in[2];
    const float* Wqg  = (const float*)d_in[3];
    const float* Wqf  = (const float*)d_in[4];
    const float* Wql  = (const float*)d_in[5];
    const float* Wk   = (const float*)d_in[6];
    const float* Wv   = (const float*)d_in[7];
    const float* Wc   = (const float*)d_in[8];
    const float* bc   = (const float*)d_in[9];
    float* out = (float*)d_out;

    static int configured = 0;
    if (!configured) {
        cudaFuncSetAttribute(proj_kv_kernel, cudaFuncAttributeMaxDynamicSharedMemorySize,
                             PROJ_SMEM_FLOATS * 4);
        cudaFuncSetAttribute(proj_one_kernel, cudaFuncAttributeMaxDynamicSharedMemorySize,
                             PROJ_SMEM_FLOATS * 4);
        cudaFuncSetAttribute(attn_kernel, cudaFuncAttributeMaxDynamicSharedMemorySize,
                             ATTN_SMEM_FLOATS * 4);
        cudaFuncSetAttribute(pointer_kernel, cudaFuncAttributeMaxDynamicSharedMemorySize,
                             PTR_SMEM_FLOATS * 4);
        configured = 1;
    }

    float* gk;  cudaGetSymbolAddress((void**)&gk, g_k);
    float* gq;  cudaGetSymbolAddress((void**)&gq, g_q);
    float* gqg; cudaGetSymbolAddress((void**)&gqg, g_qg);
    float* gwfl; cudaGetSymbolAddress((void**)&gwfl, g_Wfl);

    prep_kernel<<<(EE * 128 + 255) / 256, 256>>>(Wqf, Wql);
    qg_kernel<<<BB, 128>>>(enc, Wqg);

    proj_kv_kernel<<<800, 512, PROJ_SMEM_FLOATS * 4>>>(enc, Wk, Wv);
    proj_one_kernel<<<800, 512, PROJ_SMEM_FLOATS * 4>>>(last, gwfl, gq, nullptr, gqg);

    attn_kernel<<<dim3(BB, 2), 512, ATTN_SMEM_FLOATS * 4>>>(mask);

    proj_one_kernel<<<800, 512, PROJ_SMEM_FLOATS * 4>>>(gq, Wc, gk, bc, nullptr);

    pointer_kernel<<<BB, 1024, PTR_SMEM_FLOATS * 4>>>(enc, mask, out);
}